// round 4
// baseline (speedup 1.0000x reference)
#include <cuda_runtime.h>
#include <cstdint>

#define NN 100000
#define NE 3200000
#define FI 512
#define HH 16
#define BN_EPS 1e-5f

// ---------------- scratch (static device globals; no allocs) ----------------
__device__ float g_deg[NN];        // degree, then rsqrt(deg) in place
__device__ int   g_src[NE];
__device__ int   g_dst[NE];
__device__ float g_hw [NN * HH];   // x @ W1
__device__ float g_agg[NN * HH];   // aggregated conv1 output
__device__ float g_hw2 [NN * 2];   // (bn+relu+W2) per node
__device__ float g_agg2[NN * 2];   // aggregated conv2 output
__device__ float g_bnsum[HH];
__device__ float g_bnsq [HH];
__device__ float g_bna[HH];        // gamma * rsqrt(var+eps)
__device__ float g_bnb[HH];        // beta - mean * bna
__device__ int   g_is64;           // 1 if edge_index is int64, 0 if int32

// ---------------- dtype detection -------------------------------------------
// int64 little-endian indices < 1e5 => every odd 32-bit word is 0.
// Genuine int32 indices are uniform in [0,1e5): P(64 consecutive odd words
// all zero) ~ 0. Deterministic given the input.
__global__ void k_detect(const int* __restrict__ ei32) {
    if (threadIdx.x == 0) {
        int nz = 0;
#pragma unroll
        for (int i = 0; i < 64; i++) nz |= ei32[2 * i + 1];
        g_is64 = (nz == 0) ? 1 : 0;
    }
}

// ---------------- degree ----------------
__global__ void k_deg_init() {
    int i = blockIdx.x * blockDim.x + threadIdx.x;
    if (i < NN) g_deg[i] = 1.0f;   // self-loop
}

// decode edge index to int32 once + count in-degree
__global__ void k_edge_pass1(const void* __restrict__ eiv) {
    int e = blockIdx.x * blockDim.x + threadIdx.x;
    if (e >= NE) return;
    int s, d;
    if (g_is64) {
        const long long* ei = (const long long*)eiv;
        s = (int)ei[e];
        d = (int)ei[(size_t)NE + e];
    } else {
        const int* ei = (const int*)eiv;
        s = ei[e];
        d = ei[(size_t)NE + e];
    }
    if ((unsigned)s >= NN || (unsigned)d >= NN) { s = 0; d = 0; } // fail soft
    g_src[e] = s;
    g_dst[e] = d;
    atomicAdd(&g_deg[d], 1.0f);
}

__global__ void k_dinv() {
    int i = blockIdx.x * blockDim.x + threadIdx.x;
    if (i < NN) g_deg[i] = rsqrtf(g_deg[i]);
}

// ---------------- GEMM1: hw = x @ W1 ; agg = dinv^2 * hw (self-loop init) ---
// block: 128 threads = 32 node-groups x 4 f-groups
// tile : 256 nodes x 16 feats, K-chunks of 32
#define TBN 256
#define KC  32
__global__ void __launch_bounds__(128) k_gemm1(const float* __restrict__ x,
                                               const float* __restrict__ W1) {
    __shared__ float xs[TBN][KC + 1];   // node-major, pad 33 -> conflict-free
    __shared__ float w1c[KC * HH];      // 32x16 chunk of W1

    const int tid = threadIdx.x;
    const int ft  = tid & 3;            // 4 feats each (f = 4*ft .. +3)
    const int nt  = tid >> 2;           // 8 nodes each
    const int n0  = blockIdx.x * TBN;
    const int nbase = nt * 8;

    float acc[8][4];
#pragma unroll
    for (int i = 0; i < 8; i++)
#pragma unroll
        for (int j = 0; j < 4; j++) acc[i][j] = 0.f;

    for (int kc = 0; kc < FI; kc += KC) {
        __syncthreads();
        // load x tile (coalesced float4, transposed into padded node-major smem)
#pragma unroll
        for (int i = 0; i < 16; i++) {
            int el4 = tid + i * 128;      // 0..2047 float4s
            int nl  = el4 >> 3;
            int k4  = el4 & 7;
            int gn  = n0 + nl;
            float4 v = make_float4(0.f, 0.f, 0.f, 0.f);
            if (gn < NN)
                v = ((const float4*)(x + (size_t)gn * FI + kc))[k4];
            xs[nl][k4 * 4 + 0] = v.x;
            xs[nl][k4 * 4 + 1] = v.y;
            xs[nl][k4 * 4 + 2] = v.z;
            xs[nl][k4 * 4 + 3] = v.w;
        }
        // load W1 chunk (contiguous 512 floats)
#pragma unroll
        for (int i = 0; i < 4; i++) {
            int el = tid + i * 128;
            w1c[el] = W1[kc * HH + el];
        }
        __syncthreads();

#pragma unroll
        for (int k = 0; k < KC; k++) {
            float4 w = *(const float4*)&w1c[k * HH + ft * 4];
#pragma unroll
            for (int i = 0; i < 8; i++) {
                float xv = xs[nbase + i][k];
                acc[i][0] += xv * w.x;
                acc[i][1] += xv * w.y;
                acc[i][2] += xv * w.z;
                acc[i][3] += xv * w.w;
            }
        }
    }

    // epilogue: write hw and self-loop-initialized agg
#pragma unroll
    for (int i = 0; i < 8; i++) {
        int gn = n0 + nbase + i;
        if (gn < NN) {
            float di = g_deg[gn];
            float sl = di * di;
            float4 v = make_float4(acc[i][0], acc[i][1], acc[i][2], acc[i][3]);
            *(float4*)(g_hw  + (size_t)gn * HH + ft * 4) = v;
            float4 a = make_float4(sl * v.x, sl * v.y, sl * v.z, sl * v.w);
            *(float4*)(g_agg + (size_t)gn * HH + ft * 4) = a;
        }
    }
}

// ---------------- scatter1: agg[dst] += dinv[s]*dinv[d] * hw[src] (16 f) ----
// 4 threads per edge; dinv gathers hit the 400KB L2-resident g_deg table.
__global__ void k_scatter1() {
    long long t = (long long)blockIdx.x * blockDim.x + threadIdx.x;
    if (t >= (long long)NE * 4) return;
    int e    = (int)(t >> 2);
    int part = (int)(t & 3);
    int s = g_src[e];
    int d = g_dst[e];
    float nm = g_deg[s] * g_deg[d];
    float4 v = ((const float4*)(g_hw + (size_t)s * HH))[part];
    v.x *= nm; v.y *= nm; v.z *= nm; v.w *= nm;
    float* dp = g_agg + (size_t)d * HH + part * 4;
    asm volatile("red.global.add.v4.f32 [%0], {%1,%2,%3,%4};"
                 :: "l"(dp), "f"(v.x), "f"(v.y), "f"(v.z), "f"(v.w) : "memory");
}

// ---------------- batchnorm stats -------------------------------------------
__global__ void k_bn_zero() {
    if (threadIdx.x < HH) { g_bnsum[threadIdx.x] = 0.f; g_bnsq[threadIdx.x] = 0.f; }
}

__global__ void k_bn_stats() {
    __shared__ float ssum[HH], ssq[HH];
    int tid = threadIdx.x;
    if (tid < HH) { ssum[tid] = 0.f; ssq[tid] = 0.f; }
    __syncthreads();
    int f = tid & 15;
    float s = 0.f, q = 0.f;
    size_t stride = (size_t)gridDim.x * blockDim.x;   // multiple of 16
    for (size_t i = (size_t)blockIdx.x * blockDim.x + tid; i < (size_t)NN * HH; i += stride) {
        float v = g_agg[i];
        s += v; q += v * v;
    }
    atomicAdd(&ssum[f], s);
    atomicAdd(&ssq[f], q);
    __syncthreads();
    if (tid < HH) {
        atomicAdd(&g_bnsum[tid], ssum[tid]);
        atomicAdd(&g_bnsq[tid],  ssq[tid]);
    }
}

// b1 cancels in BN (constant shift removed by mean subtraction)
__global__ void k_bn_fin(const float* __restrict__ gamma, const float* __restrict__ beta) {
    int f = threadIdx.x;
    if (f >= HH) return;
    float mean = g_bnsum[f] / (float)NN;
    float var  = g_bnsq[f] / (float)NN - mean * mean;
    float a = gamma[f] * rsqrtf(var + BN_EPS);
    g_bna[f] = a;
    g_bnb[f] = beta[f] - mean * a;
}

// ---------------- bn + relu + GEMM2 + self-loop init ------------------------
__global__ void k_fused2(const float* __restrict__ W2) {
    __shared__ float a[HH], b[HH], w2[HH * 2];
    int tid = threadIdx.x;
    if (tid < HH) { a[tid] = g_bna[tid]; b[tid] = g_bnb[tid]; }
    if (tid < HH * 2) w2[tid] = W2[tid];
    __syncthreads();
    int n = blockIdx.x * blockDim.x + tid;
    if (n >= NN) return;
    const float4* hp = (const float4*)(g_agg + (size_t)n * HH);
    float acc0 = 0.f, acc1 = 0.f;
#pragma unroll
    for (int p = 0; p < 4; p++) {
        float4 h = hp[p];
        float v0 = fmaxf(a[p * 4 + 0] * h.x + b[p * 4 + 0], 0.f);
        float v1 = fmaxf(a[p * 4 + 1] * h.y + b[p * 4 + 1], 0.f);
        float v2 = fmaxf(a[p * 4 + 2] * h.z + b[p * 4 + 2], 0.f);
        float v3 = fmaxf(a[p * 4 + 3] * h.w + b[p * 4 + 3], 0.f);
        acc0 += v0 * w2[(p * 4 + 0) * 2] + v1 * w2[(p * 4 + 1) * 2]
              + v2 * w2[(p * 4 + 2) * 2] + v3 * w2[(p * 4 + 3) * 2];
        acc1 += v0 * w2[(p * 4 + 0) * 2 + 1] + v1 * w2[(p * 4 + 1) * 2 + 1]
              + v2 * w2[(p * 4 + 2) * 2 + 1] + v3 * w2[(p * 4 + 3) * 2 + 1];
    }
    g_hw2[2 * n]     = acc0;
    g_hw2[2 * n + 1] = acc1;
    float di = g_deg[n];
    float sl = di * di;
    g_agg2[2 * n]     = sl * acc0;
    g_agg2[2 * n + 1] = sl * acc1;
}

// ---------------- scatter2: agg2[dst] += dinv[s]*dinv[d] * hw2[src] ---------
__global__ void k_scatter2() {
    int e = blockIdx.x * blockDim.x + threadIdx.x;
    if (e >= NE) return;
    int s = g_src[e];
    int d = g_dst[e];
    float nm = g_deg[s] * g_deg[d];
    float2 v = ((const float2*)g_hw2)[s];
    v.x *= nm; v.y *= nm;
    float* dp = g_agg2 + (size_t)d * 2;
    asm volatile("red.global.add.v2.f32 [%0], {%1,%2};"
                 :: "l"(dp), "f"(v.x), "f"(v.y) : "memory");
}

// ---------------- output: + b2, log_softmax ---------------------------------
__global__ void k_out(const float* __restrict__ b2, float* __restrict__ out) {
    int n = blockIdx.x * blockDim.x + threadIdx.x;
    if (n >= NN) return;
    float z0 = g_agg2[2 * n]     + b2[0];
    float z1 = g_agg2[2 * n + 1] + b2[1];
    float m  = fmaxf(z0, z1);
    float l  = m + logf(expf(z0 - m) + expf(z1 - m));
    out[2 * n]     = z0 - l;
    out[2 * n + 1] = z1 - l;
}

// ---------------- launcher ---------------------------------------------------
extern "C" void kernel_launch(void* const* d_in, const int* in_sizes, int n_in,
                              void* d_out, int out_size) {
    const float* x     = (const float*)d_in[0];
    const void*  ei    = d_in[1];                  // int32 or int64, detected on device
    const float* W1    = (const float*)d_in[2];
    // d_in[3] = b1 : cancels under BN mean subtraction
    const float* gamma = (const float*)d_in[4];
    const float* beta  = (const float*)d_in[5];
    const float* W2    = (const float*)d_in[6];
    const float* b2    = (const float*)d_in[7];
    float* out = (float*)d_out;

    const int TB = 256;
    k_detect    <<<1, 32>>>((const int*)ei);
    k_deg_init  <<<(NN + TB - 1) / TB, TB>>>();
    k_edge_pass1<<<(NE + TB - 1) / TB, TB>>>(ei);
    k_dinv      <<<(NN + TB - 1) / TB, TB>>>();
    k_gemm1     <<<(NN + TBN - 1) / TBN, 128>>>(x, W1);
    {
        long long tot = (long long)NE * 4;
        k_scatter1<<<(unsigned)((tot + TB - 1) / TB), TB>>>();
    }
    k_bn_zero   <<<1, 32>>>();
    k_bn_stats  <<<512, 256>>>();
    k_bn_fin    <<<1, 32>>>(gamma, beta);
    k_fused2    <<<(NN + TB - 1) / TB, TB>>>(W2);
    k_scatter2  <<<(NE + TB - 1) / TB, TB>>>();
    k_out       <<<(NN + TB - 1) / TB, TB>>>(b2, out);
}